// round 8
// baseline (speedup 1.0000x reference)
#include <cuda_runtime.h>

// Laplacian_Forward_Model: per-image 3x3 conv + two normalize passes + floor.
// One CTA per (image, mult-variant). 64 threads, 16 px/thread (rows g and g+16).
//
// input (B,1,32,32) f32; weight (n_mult,9); weight_factor (n_mult,1);
// output (n_mult,B,1,32,32) f32.

#define TPB   64
#define PITCH 36   // 34 rows x 36 cols; conflict-free LDS.128

// Order-preserving float<->int map (self-inverse, monotone for finite values).
__device__ __forceinline__ int f2ord(float x) {
    int b = __float_as_int(x);
    return b ^ ((b >> 31) & 0x7FFFFFFF);
}
__device__ __forceinline__ float ord2f(int k) {
    return __int_as_float(k ^ ((k >> 31) & 0x7FFFFFFF));
}
// FFMA with free [0,1] saturation.
__device__ __forceinline__ float fma_sat(float a, float b, float c) {
    float r;
    asm("fma.rn.sat.f32 %0, %1, %2, %3;" : "=f"(r) : "f"(a), "f"(b), "f"(c));
    return r;
}

__global__ __launch_bounds__(TPB, 16)
void lap_fwd_kernel(const float* __restrict__ in,
                    const float* __restrict__ weight,
                    const float* __restrict__ wfac,
                    float* __restrict__ out,
                    int B)
{
    __shared__ float img[PITCH * 34];
    __shared__ __align__(16) float ksm[12];
    __shared__ __align__(8) int rmn[2], rmx[2], rmn2[2], rmx2[2];

    const int tid  = threadIdx.x;
    const int lane = tid & 31;
    const int wrp  = tid >> 5;
    const int g    = tid >> 2;        // 0..15
    const int c    = tid & 3;         // col-group
    const int x0   = c << 3;
    const int b    = blockIdx.x;
    const int ii   = blockIdx.y;
    const unsigned FULL = 0xffffffffu;

    // ---- 9 threads compute the clamped 3x3 kernel into smem ----
    if (tid < 9) {
        float wfv = fminf(fmaxf(wfac[ii], 1.001f), 254.999f);
        float w   = weight[ii * 9 + tid];
        ksm[tid]  = fminf(fmaxf(w, -0.999f), 0.999f) * wfv;
    }
    // ---- zero vertical halo rows 0 and 33 ----
    if (tid < 16) {
        int row = (tid < 8) ? 0 : 33;
        int col = (tid & 7) << 2;
        *reinterpret_cast<float4*>(&img[row * PITCH + col]) = make_float4(0.f, 0.f, 0.f, 0.f);
    }
    // ---- stage 32x32 image: 256 float4, 4 per thread ----
    const float4* src = reinterpret_cast<const float4*>(in + (size_t)b * 1024);
#pragma unroll
    for (int q = 0; q < 4; ++q) {
        int i = tid + q * TPB;            // float4 index 0..255
        float4 v = src[i];
        *reinterpret_cast<float4*>(&img[((i >> 3) + 1) * PITCH + ((i & 7) << 2)]) = v;
    }
    __syncthreads();

    // ---- pull kernel weights from smem (broadcast LDS) ----
    float k[9];
    {
        float4 a = *reinterpret_cast<float4*>(ksm);
        float4 d = *reinterpret_cast<float4*>(ksm + 4);
        k[0] = a.x; k[1] = a.y; k[2] = a.z; k[3] = a.w;
        k[4] = d.x; k[5] = d.y; k[6] = d.z; k[7] = d.w; k[8] = ksm[8];
    }

    // ---- 3x3 correlation for rows g and g+16, 8 px each ----
    float cv[16], xv[16];
#pragma unroll
    for (int j = 0; j < 16; ++j) cv[j] = 0.f;

#pragma unroll
    for (int half = 0; half < 2; ++half) {
        const int rr = half ? (g + 16) : g;   // image row; smem row = rr+t (halo shift)
#pragma unroll
        for (int t = 0; t < 3; ++t) {
            const float* row = &img[(rr + t) * PITCH + x0];
            float4 A  = *reinterpret_cast<const float4*>(row);
            float4 Bv = *reinterpret_cast<const float4*>(row + 4);
            float L = __shfl_up_sync(FULL, Bv.w, 1);
            float R = __shfl_down_sync(FULL, A.x, 1);
            if (c == 0) L = 0.f;
            if (c == 3) R = 0.f;
            float w[10] = {L, A.x, A.y, A.z, A.w, Bv.x, Bv.y, Bv.z, Bv.w, R};
            float k0 = k[3 * t], k1 = k[3 * t + 1], k2 = k[3 * t + 2];
#pragma unroll
            for (int j = 0; j < 8; ++j)
                cv[half * 8 + j] += k0 * w[j] + k1 * w[j + 1] + k2 * w[j + 2];
            if (t == 1) {
#pragma unroll
                for (int j = 0; j < 8; ++j) xv[half * 8 + j] = w[j + 1];
            }
        }
    }

    // ---- reduction 1: min/max of conv (local tree + REDUX.S32 + 2-warp combine) ----
    float mn = cv[0], mx = cv[0];
#pragma unroll
    for (int j = 1; j < 16; ++j) { mn = fminf(mn, cv[j]); mx = fmaxf(mx, cv[j]); }
    int mni = __reduce_min_sync(FULL, f2ord(mn));
    int mxi = __reduce_max_sync(FULL, f2ord(mx));
    if (lane == 0) { rmn[wrp] = mni; rmx[wrp] = mxi; }
    __syncthreads();
    int2 a1 = *reinterpret_cast<int2*>(rmn);
    int2 b1 = *reinterpret_cast<int2*>(rmx);
    float cmin = ord2f(min(a1.x, a1.y));
    float cmax = ord2f(max(b1.x, b1.y));

    // ---- sharpen: sh = x + (conv - cmin) * (255/den1) ----
    float s1 = 255.0f / fmaxf(cmax - cmin, 1e-6f);   // block-uniform
    float sh[16];
#pragma unroll
    for (int j = 0; j < 16; ++j)
        sh[j] = fmaf(cv[j] - cmin, s1, xv[j]);

    // ---- reduction 2: min/max of sharpened ----
    mn = sh[0]; mx = sh[0];
#pragma unroll
    for (int j = 1; j < 16; ++j) { mn = fminf(mn, sh[j]); mx = fmaxf(mx, sh[j]); }
    mni = __reduce_min_sync(FULL, f2ord(mn));
    mxi = __reduce_max_sync(FULL, f2ord(mx));
    if (lane == 0) { rmn2[wrp] = mni; rmx2[wrp] = mxi; }
    __syncthreads();
    a1 = *reinterpret_cast<int2*>(rmn2);
    b1 = *reinterpret_cast<int2*>(rmx2);
    float smin = ord2f(min(a1.x, a1.y));
    float smax = ord2f(max(b1.x, b1.y));

    // ---- final: u = sat((sh - smin)/den2); out = floor(255*u); 4x STG.128 ----
    float invd = 1.0f / fminf(fmaxf(smax - smin, 1e-6f), 255.0f);
    float d2   = -smin * invd;
    float* dst = out + ((size_t)ii * B + b) * 1024;
    float v[16];
#pragma unroll
    for (int j = 0; j < 16; ++j) {
        float u = fma_sat(sh[j], invd, d2);     // clamp [0,1] free
        v[j] = floorf(u * 255.0f);
    }
    float* dA = dst + g * 32 + x0;              // row g
    float* dB = dst + (g + 16) * 32 + x0;       // row g+16
    reinterpret_cast<float4*>(dA)[0] = make_float4(v[0],  v[1],  v[2],  v[3]);
    reinterpret_cast<float4*>(dA)[1] = make_float4(v[4],  v[5],  v[6],  v[7]);
    reinterpret_cast<float4*>(dB)[0] = make_float4(v[8],  v[9],  v[10], v[11]);
    reinterpret_cast<float4*>(dB)[1] = make_float4(v[12], v[13], v[14], v[15]);
}

extern "C" void kernel_launch(void* const* d_in, const int* in_sizes, int n_in,
                              void* d_out, int out_size)
{
    const float* in  = (const float*)d_in[0];
    const float* w   = (const float*)d_in[1];
    const float* wf  = (const float*)d_in[2];
    float* out       = (float*)d_out;

    int B      = in_sizes[0] / 1024;
    int n_mult = in_sizes[1] / 9;

    dim3 grid(B, n_mult);
    lap_fwd_kernel<<<grid, TPB>>>(in, w, wf, out, B);
}

// round 10
// speedup vs baseline: 1.0087x; 1.0087x over previous
#include <cuda_runtime.h>

// Laplacian_Forward_Model: per-image 3x3 conv + two normalize passes + floor.
// One CTA per (image, mult-variant). 128 threads, 8 contiguous pixels/thread.
// R10 = resubmit of R9 (infra failure): R7 topology (128thr/32reg/occ90%) +
// R8 instruction cuts (smem kernel setup, fma.sat final, REDUX.S32 reductions).

#define TPB   128
#define PITCH 36   // 34 rows x 36 cols; conflict-free LDS.128

// Order-preserving float<->int map (self-inverse, monotone for finite values).
__device__ __forceinline__ int f2ord(float x) {
    int b = __float_as_int(x);
    return b ^ ((b >> 31) & 0x7FFFFFFF);
}
__device__ __forceinline__ float ord2f(int k) {
    return __int_as_float(k ^ ((k >> 31) & 0x7FFFFFFF));
}
// FFMA with free [0,1] saturation.
__device__ __forceinline__ float fma_sat(float a, float b, float c) {
    float r;
    asm("fma.rn.sat.f32 %0, %1, %2, %3;" : "=f"(r) : "f"(a), "f"(b), "f"(c));
    return r;
}

__global__ __launch_bounds__(TPB, 14)
void lap_fwd_kernel(const float* __restrict__ in,
                    const float* __restrict__ weight,
                    const float* __restrict__ wfac,
                    float* __restrict__ out,
                    int B)
{
    __shared__ float img[PITCH * 34];
    __shared__ __align__(16) float ksm[12];
    __shared__ __align__(16) int rmn1[4], rmx1[4], rmn2[4], rmx2[4];

    const int tid  = threadIdx.x;
    const int lane = tid & 31;
    const int wrp  = tid >> 5;
    const int r    = tid >> 2;        // pixel row 0..31
    const int c    = tid & 3;         // col-group 0..3
    const int x0   = c << 3;
    const int b    = blockIdx.x;
    const int ii   = blockIdx.y;
    const unsigned FULL = 0xffffffffu;

    // ---- 9 threads compute the clamped 3x3 kernel into smem ----
    if (tid < 9) {
        float wfv = fminf(fmaxf(wfac[ii], 1.001f), 254.999f);
        float w   = weight[ii * 9 + tid];
        ksm[tid]  = fminf(fmaxf(w, -0.999f), 0.999f) * wfv;
    }
    // ---- zero vertical halo rows 0 and 33 (cols 0..31) ----
    if (tid < 16) {
        int row = (tid < 8) ? 0 : 33;
        int col = (tid & 7) << 2;
        *reinterpret_cast<float4*>(&img[row * PITCH + col]) = make_float4(0.f, 0.f, 0.f, 0.f);
    }
    // ---- stage 32x32 image: 256 float4, 2 per thread ----
    const float4* src = reinterpret_cast<const float4*>(in + (size_t)b * 1024);
#pragma unroll
    for (int q = 0; q < 2; ++q) {
        int i = tid + q * TPB;            // float4 index 0..255
        float4 v = src[i];
        *reinterpret_cast<float4*>(&img[((i >> 3) + 1) * PITCH + ((i & 7) << 2)]) = v;
    }
    __syncthreads();

    // ---- pull kernel weights from smem (broadcast LDS) ----
    float k[9];
    {
        float4 a = *reinterpret_cast<float4*>(ksm);
        float4 d = *reinterpret_cast<float4*>(ksm + 4);
        k[0] = a.x; k[1] = a.y; k[2] = a.z; k[3] = a.w;
        k[4] = d.x; k[5] = d.y; k[6] = d.z; k[7] = d.w; k[8] = ksm[8];
    }

    // ---- 3x3 correlation, 8 pixels/thread: 2x LDS.128 + edge shfl per row ----
    float conv[8];
#pragma unroll
    for (int j = 0; j < 8; ++j) conv[j] = 0.f;

#pragma unroll
    for (int t = 0; t < 3; ++t) {
        const float* row = &img[(r + t) * PITCH + x0];
        float4 A  = *reinterpret_cast<const float4*>(row);
        float4 Bv = *reinterpret_cast<const float4*>(row + 4);
        float L = __shfl_up_sync(FULL, Bv.w, 1);
        float R = __shfl_down_sync(FULL, A.x, 1);
        if (c == 0) L = 0.f;
        if (c == 3) R = 0.f;
        float w[10] = {L, A.x, A.y, A.z, A.w, Bv.x, Bv.y, Bv.z, Bv.w, R};
        float k0 = k[3 * t], k1 = k[3 * t + 1], k2 = k[3 * t + 2];
#pragma unroll
        for (int j = 0; j < 8; ++j)
            conv[j] += k0 * w[j] + k1 * w[j + 1] + k2 * w[j + 2];
    }

    // ---- reduction 1: min/max of conv (REDUX.S32 + 4-warp LDS.128 combine) ----
    float mn = conv[0], mx = conv[0];
#pragma unroll
    for (int j = 1; j < 8; ++j) { mn = fminf(mn, conv[j]); mx = fmaxf(mx, conv[j]); }
    int mni = __reduce_min_sync(FULL, f2ord(mn));
    int mxi = __reduce_max_sync(FULL, f2ord(mx));
    if (lane == 0) { rmn1[wrp] = mni; rmx1[wrp] = mxi; }
    __syncthreads();
    int4 m4 = *reinterpret_cast<int4*>(rmn1);
    int4 M4 = *reinterpret_cast<int4*>(rmx1);
    float cmin = ord2f(min(min(m4.x, m4.y), min(m4.z, m4.w)));
    float cmax = ord2f(max(max(M4.x, M4.y), max(M4.z, M4.w)));

    // ---- sharpen: sh = x + (conv - cmin) * (255/den1)  (x reloaded from smem) ----
    float s1 = 255.0f / fmaxf(cmax - cmin, 1e-6f);   // block-uniform
    float sh[8];
    {
        const float* row = &img[(r + 1) * PITCH + x0];
        float4 A  = *reinterpret_cast<const float4*>(row);
        float4 Bv = *reinterpret_cast<const float4*>(row + 4);
        float xv[8] = {A.x, A.y, A.z, A.w, Bv.x, Bv.y, Bv.z, Bv.w};
#pragma unroll
        for (int j = 0; j < 8; ++j)
            sh[j] = fmaf(conv[j] - cmin, s1, xv[j]);
    }

    // ---- reduction 2: min/max of sharpened ----
    mn = sh[0]; mx = sh[0];
#pragma unroll
    for (int j = 1; j < 8; ++j) { mn = fminf(mn, sh[j]); mx = fmaxf(mx, sh[j]); }
    mni = __reduce_min_sync(FULL, f2ord(mn));
    mxi = __reduce_max_sync(FULL, f2ord(mx));
    if (lane == 0) { rmn2[wrp] = mni; rmx2[wrp] = mxi; }
    __syncthreads();
    m4 = *reinterpret_cast<int4*>(rmn2);
    M4 = *reinterpret_cast<int4*>(rmx2);
    float smin = ord2f(min(min(m4.x, m4.y), min(m4.z, m4.w)));
    float smax = ord2f(max(max(M4.x, M4.y), max(M4.z, M4.w)));

    // ---- final: u = sat((sh - smin)*invd); out = floor(255*u); 2x STG.128 ----
    float invd = 1.0f / fminf(fmaxf(smax - smin, 1e-6f), 255.0f);
    float d2   = -smin * invd;
    float* dst = out + ((size_t)ii * B + b) * 1024 + r * 32 + x0;
    float v[8];
#pragma unroll
    for (int j = 0; j < 8; ++j) {
        float u = fma_sat(sh[j], invd, d2);   // free [0,1] clamp
        v[j] = floorf(u * 255.0f);
    }
    reinterpret_cast<float4*>(dst)[0] = make_float4(v[0], v[1], v[2], v[3]);
    reinterpret_cast<float4*>(dst)[1] = make_float4(v[4], v[5], v[6], v[7]);
}

extern "C" void kernel_launch(void* const* d_in, const int* in_sizes, int n_in,
                              void* d_out, int out_size)
{
    const float* in  = (const float*)d_in[0];
    const float* w   = (const float*)d_in[1];
    const float* wf  = (const float*)d_in[2];
    float* out       = (float*)d_out;

    int B      = in_sizes[0] / 1024;
    int n_mult = in_sizes[1] / 9;

    dim3 grid(B, n_mult);
    lap_fwd_kernel<<<grid, TPB>>>(in, w, wf, out, B);
}

// round 11
// speedup vs baseline: 1.0397x; 1.0308x over previous
#include <cuda_runtime.h>

// Laplacian_Forward_Model — warp-per-image, barrier-free.
// 128 threads = 4 warps = 4 images per CTA. Each warp owns a private smem
// tile; reductions are pure REDUX.S32 over the warp (no BAR.SYNC anywhere).
// Thread (r = lane>>2, c = lane&3) handles rows r, r+8, r+16, r+24, 8 px each.
//
// input (B,1,32,32) f32; weight (n_mult,9); weight_factor (n_mult,1);
// output (n_mult,B,1,32,32) f32.

#define TPB   128
#define PITCH 36   // words per tile row; conflict-free LDS.128 for this layout
#define TROWS 34   // 32 rows + top/bottom zero halo

// Order-preserving float<->int map (self-inverse, monotone for finite values).
__device__ __forceinline__ int f2ord(float x) {
    int b = __float_as_int(x);
    return b ^ ((b >> 31) & 0x7FFFFFFF);
}
__device__ __forceinline__ float ord2f(int k) {
    return __int_as_float(k ^ ((k >> 31) & 0x7FFFFFFF));
}
// FFMA with free [0,1] saturation.
__device__ __forceinline__ float fma_sat(float a, float b, float c) {
    float r;
    asm("fma.rn.sat.f32 %0, %1, %2, %3;" : "=f"(r) : "f"(a), "f"(b), "f"(c));
    return r;
}

__global__ __launch_bounds__(TPB, 8)
void lap_fwd_kernel(const float* __restrict__ in,
                    const float* __restrict__ weight,
                    const float* __restrict__ wfac,
                    float* __restrict__ out,
                    int B)
{
    __shared__ float tiles[4][TROWS * PITCH];

    const int tid  = threadIdx.x;
    const int wid  = tid >> 5;
    const int lane = tid & 31;
    const int r    = lane >> 2;       // base row 0..7
    const int c    = lane & 3;        // col-group 0..3
    const int x0   = c << 3;
    const int b    = blockIdx.x * 4 + wid;   // image index (one per warp)
    const int ii   = blockIdx.y;
    const unsigned FULL = 0xffffffffu;

    if (b >= B) return;               // warp-uniform; no barriers below
    float* tile = tiles[wid];

    // ---- clamped 3x3 kernel (broadcast loads, every thread) ----
    float wfv = fminf(fmaxf(wfac[ii], 1.001f), 254.999f);
    float k[9];
#pragma unroll
    for (int j = 0; j < 9; ++j) {
        float w = weight[ii * 9 + j];
        k[j] = fminf(fmaxf(w, -0.999f), 0.999f) * wfv;
    }

    // ---- zero halo rows 0 and 33 (cols 0..31) ----
    if (lane < 16) {
        int row = (lane < 8) ? 0 : 33;
        int col = (lane & 7) << 2;
        *reinterpret_cast<float4*>(&tile[row * PITCH + col]) = make_float4(0.f, 0.f, 0.f, 0.f);
    }

    // ---- stage the 32x32 image: 256 float4, 8 per lane, coalesced ----
    const float4* src = reinterpret_cast<const float4*>(in + (size_t)b * 1024);
#pragma unroll
    for (int q = 0; q < 8; ++q) {
        int i = lane + (q << 5);          // float4 index 0..255
        float4 v = src[i];
        *reinterpret_cast<float4*>(&tile[((i >> 3) + 1) * PITCH + ((i & 7) << 2)]) = v;
    }
    __syncwarp();

    // ---- 3x3 correlation: 4 row-slices (r+8s), 8 px each ----
    float cv[32];
#pragma unroll
    for (int j = 0; j < 32; ++j) cv[j] = 0.f;

#pragma unroll
    for (int s = 0; s < 4; ++s) {
#pragma unroll
        for (int t = 0; t < 3; ++t) {
            const float* row = &tile[(r + 8 * s + t) * PITCH + x0];
            float4 A  = *reinterpret_cast<const float4*>(row);
            float4 Bv = *reinterpret_cast<const float4*>(row + 4);
            float L = __shfl_up_sync(FULL, Bv.w, 1);
            float R = __shfl_down_sync(FULL, A.x, 1);
            if (c == 0) L = 0.f;
            if (c == 3) R = 0.f;
            float w[10] = {L, A.x, A.y, A.z, A.w, Bv.x, Bv.y, Bv.z, Bv.w, R};
            float k0 = k[3 * t], k1 = k[3 * t + 1], k2 = k[3 * t + 2];
#pragma unroll
            for (int j = 0; j < 8; ++j)
                cv[s * 8 + j] += k0 * w[j] + k1 * w[j + 1] + k2 * w[j + 2];
        }
    }

    // ---- reduction 1: min/max of conv over image = warp REDUX only ----
    float mn = cv[0], mx = cv[0];
#pragma unroll
    for (int j = 1; j < 32; ++j) { mn = fminf(mn, cv[j]); mx = fmaxf(mx, cv[j]); }
    float cmin = ord2f(__reduce_min_sync(FULL, f2ord(mn)));
    float cmax = ord2f(__reduce_max_sync(FULL, f2ord(mx)));

    // ---- sharpen in place: sh = x + (conv - cmin) * (255/den1) ----
    float s1 = 255.0f / fmaxf(cmax - cmin, 1e-6f);   // warp-uniform
#pragma unroll
    for (int s = 0; s < 4; ++s) {
        const float* row = &tile[(r + 8 * s + 1) * PITCH + x0];
        float4 A  = *reinterpret_cast<const float4*>(row);
        float4 Bv = *reinterpret_cast<const float4*>(row + 4);
        float xv[8] = {A.x, A.y, A.z, A.w, Bv.x, Bv.y, Bv.z, Bv.w};
#pragma unroll
        for (int j = 0; j < 8; ++j)
            cv[s * 8 + j] = fmaf(cv[s * 8 + j] - cmin, s1, xv[j]);
    }

    // ---- reduction 2: min/max of sharpened = warp REDUX only ----
    mn = cv[0]; mx = cv[0];
#pragma unroll
    for (int j = 1; j < 32; ++j) { mn = fminf(mn, cv[j]); mx = fmaxf(mx, cv[j]); }
    float smin = ord2f(__reduce_min_sync(FULL, f2ord(mn)));
    float smax = ord2f(__reduce_max_sync(FULL, f2ord(mx)));

    // ---- final: u = sat((sh - smin)*invd); out = floor(255*u); 8x STG.128 ----
    float invd = 1.0f / fminf(fmaxf(smax - smin, 1e-6f), 255.0f);
    float d2   = -smin * invd;
    float* dst = out + ((size_t)ii * B + b) * 1024;
#pragma unroll
    for (int s = 0; s < 4; ++s) {
        float v[8];
#pragma unroll
        for (int j = 0; j < 8; ++j) {
            float u = fma_sat(cv[s * 8 + j], invd, d2);   // free [0,1] clamp
            v[j] = floorf(u * 255.0f);
        }
        float* p = dst + (r + 8 * s) * 32 + x0;
        reinterpret_cast<float4*>(p)[0] = make_float4(v[0], v[1], v[2], v[3]);
        reinterpret_cast<float4*>(p)[1] = make_float4(v[4], v[5], v[6], v[7]);
    }
}

extern "C" void kernel_launch(void* const* d_in, const int* in_sizes, int n_in,
                              void* d_out, int out_size)
{
    const float* in  = (const float*)d_in[0];
    const float* w   = (const float*)d_in[1];
    const float* wf  = (const float*)d_in[2];
    float* out       = (float*)d_out;

    int B      = in_sizes[0] / 1024;
    int n_mult = in_sizes[1] / 9;

    dim3 grid((B + 3) / 4, n_mult);
    lap_fwd_kernel<<<grid, TPB>>>(in, w, wf, out, B);
}

// round 13
// speedup vs baseline: 1.0650x; 1.0244x over previous
#include <cuda_runtime.h>

// Laplacian_Forward_Model — warp-per-image, barrier-free + L2 residency mgmt.
// R13 = R12 with the sm_103-legal 32B evict_last load form (.v8.b32):
// input pinned L2-resident across graph replays, output streamed (evict-first).

#define TPB   128
#define PITCH 36   // words per tile row; conflict-free LDS.128 for this layout
#define TROWS 34   // 32 rows + top/bottom zero halo

// Order-preserving float<->int map (self-inverse, monotone for finite values).
__device__ __forceinline__ int f2ord(float x) {
    int b = __float_as_int(x);
    return b ^ ((b >> 31) & 0x7FFFFFFF);
}
__device__ __forceinline__ float ord2f(int k) {
    return __int_as_float(k ^ ((k >> 31) & 0x7FFFFFFF));
}
// FFMA with free [0,1] saturation.
__device__ __forceinline__ float fma_sat(float a, float b, float c) {
    float r;
    asm("fma.rn.sat.f32 %0, %1, %2, %3;" : "=f"(r) : "f"(a), "f"(b), "f"(c));
    return r;
}
// 32B load, L2 evict_last (sm_103 requires .v8.b32 for this hint).
struct f8 { float4 a, b; };
__device__ __forceinline__ f8 ldg_evl8(const float* p) {
    unsigned r0, r1, r2, r3, r4, r5, r6, r7;
    asm volatile("ld.global.nc.L2::evict_last.v8.b32 {%0,%1,%2,%3,%4,%5,%6,%7}, [%8];"
                 : "=r"(r0), "=r"(r1), "=r"(r2), "=r"(r3),
                   "=r"(r4), "=r"(r5), "=r"(r6), "=r"(r7) : "l"(p));
    f8 v;
    v.a = make_float4(__uint_as_float(r0), __uint_as_float(r1),
                      __uint_as_float(r2), __uint_as_float(r3));
    v.b = make_float4(__uint_as_float(r4), __uint_as_float(r5),
                      __uint_as_float(r6), __uint_as_float(r7));
    return v;
}
// 16B store, streaming (evict-first: don't let output evict the input).
__device__ __forceinline__ void stg_cs(float4* p, float4 v) {
    asm volatile("st.global.cs.v4.f32 [%0], {%1,%2,%3,%4};"
                 :: "l"(p), "f"(v.x), "f"(v.y), "f"(v.z), "f"(v.w) : "memory");
}

__global__ __launch_bounds__(TPB, 8)
void lap_fwd_kernel(const float* __restrict__ in,
                    const float* __restrict__ weight,
                    const float* __restrict__ wfac,
                    float* __restrict__ out,
                    int B)
{
    __shared__ float tiles[4][TROWS * PITCH];

    const int tid  = threadIdx.x;
    const int wid  = tid >> 5;
    const int lane = tid & 31;
    const int r    = lane >> 2;       // base row 0..7
    const int c    = lane & 3;        // col-group 0..3
    const int x0   = c << 3;
    const int b    = blockIdx.x * 4 + wid;   // image index (one per warp)
    const int ii   = blockIdx.y;
    const unsigned FULL = 0xffffffffu;

    if (b >= B) return;               // warp-uniform; no barriers below
    float* tile = tiles[wid];

    // ---- clamped 3x3 kernel (broadcast loads, every thread) ----
    float wfv = fminf(fmaxf(wfac[ii], 1.001f), 254.999f);
    float k[9];
#pragma unroll
    for (int j = 0; j < 9; ++j) {
        float w = weight[ii * 9 + j];
        k[j] = fminf(fmaxf(w, -0.999f), 0.999f) * wfv;
    }

    // ---- zero halo rows 0 and 33 (cols 0..31) ----
    if (lane < 16) {
        int row = (lane < 8) ? 0 : 33;
        int col = (lane & 7) << 2;
        *reinterpret_cast<float4*>(&tile[row * PITCH + col]) = make_float4(0.f, 0.f, 0.f, 0.f);
    }

    // ---- stage the 32x32 image: 128 x 32B loads, 4 per lane, coalesced ----
    const float* src = in + (size_t)b * 1024;
#pragma unroll
    for (int q = 0; q < 4; ++q) {
        int i = lane + (q << 5);          // float8 index 0..127
        f8 v = ldg_evl8(src + (i << 3));
        int y = i >> 2;                   // row 0..31
        int x = (i & 3) << 3;             // 0,8,16,24
        float* d = &tile[(y + 1) * PITCH + x];
        *reinterpret_cast<float4*>(d)     = v.a;
        *reinterpret_cast<float4*>(d + 4) = v.b;
    }
    __syncwarp();

    // ---- 3x3 correlation: 4 row-slices (r+8s), 8 px each ----
    float cv[32];
#pragma unroll
    for (int j = 0; j < 32; ++j) cv[j] = 0.f;

#pragma unroll
    for (int s = 0; s < 4; ++s) {
#pragma unroll
        for (int t = 0; t < 3; ++t) {
            const float* row = &tile[(r + 8 * s + t) * PITCH + x0];
            float4 A  = *reinterpret_cast<const float4*>(row);
            float4 Bv = *reinterpret_cast<const float4*>(row + 4);
            float L = __shfl_up_sync(FULL, Bv.w, 1);
            float R = __shfl_down_sync(FULL, A.x, 1);
            if (c == 0) L = 0.f;
            if (c == 3) R = 0.f;
            float w[10] = {L, A.x, A.y, A.z, A.w, Bv.x, Bv.y, Bv.z, Bv.w, R};
            float k0 = k[3 * t], k1 = k[3 * t + 1], k2 = k[3 * t + 2];
#pragma unroll
            for (int j = 0; j < 8; ++j)
                cv[s * 8 + j] += k0 * w[j] + k1 * w[j + 1] + k2 * w[j + 2];
        }
    }

    // ---- reduction 1: min/max of conv over image = warp REDUX only ----
    float mn = cv[0], mx = cv[0];
#pragma unroll
    for (int j = 1; j < 32; ++j) { mn = fminf(mn, cv[j]); mx = fmaxf(mx, cv[j]); }
    float cmin = ord2f(__reduce_min_sync(FULL, f2ord(mn)));
    float cmax = ord2f(__reduce_max_sync(FULL, f2ord(mx)));

    // ---- sharpen in place: sh = x + (conv - cmin) * (255/den1) ----
    float s1 = 255.0f / fmaxf(cmax - cmin, 1e-6f);   // warp-uniform
#pragma unroll
    for (int s = 0; s < 4; ++s) {
        const float* row = &tile[(r + 8 * s + 1) * PITCH + x0];
        float4 A  = *reinterpret_cast<const float4*>(row);
        float4 Bv = *reinterpret_cast<const float4*>(row + 4);
        float xv[8] = {A.x, A.y, A.z, A.w, Bv.x, Bv.y, Bv.z, Bv.w};
#pragma unroll
        for (int j = 0; j < 8; ++j)
            cv[s * 8 + j] = fmaf(cv[s * 8 + j] - cmin, s1, xv[j]);
    }

    // ---- reduction 2: min/max of sharpened = warp REDUX only ----
    mn = cv[0]; mx = cv[0];
#pragma unroll
    for (int j = 1; j < 32; ++j) { mn = fminf(mn, cv[j]); mx = fmaxf(mx, cv[j]); }
    float smin = ord2f(__reduce_min_sync(FULL, f2ord(mn)));
    float smax = ord2f(__reduce_max_sync(FULL, f2ord(mx)));

    // ---- final: u = sat((sh - smin)*invd); out = floor(255*u); 8x STG.cs ----
    float invd = 1.0f / fminf(fmaxf(smax - smin, 1e-6f), 255.0f);
    float d2   = -smin * invd;
    float* dst = out + ((size_t)ii * B + b) * 1024;
#pragma unroll
    for (int s = 0; s < 4; ++s) {
        float v[8];
#pragma unroll
        for (int j = 0; j < 8; ++j) {
            float u = fma_sat(cv[s * 8 + j], invd, d2);   // free [0,1] clamp
            v[j] = floorf(u * 255.0f);
        }
        float* p = dst + (r + 8 * s) * 32 + x0;
        stg_cs(reinterpret_cast<float4*>(p) + 0, make_float4(v[0], v[1], v[2], v[3]));
        stg_cs(reinterpret_cast<float4*>(p) + 1, make_float4(v[4], v[5], v[6], v[7]));
    }
}

extern "C" void kernel_launch(void* const* d_in, const int* in_sizes, int n_in,
                              void* d_out, int out_size)
{
    const float* in  = (const float*)d_in[0];
    const float* w   = (const float*)d_in[1];
    const float* wf  = (const float*)d_in[2];
    float* out       = (float*)d_out;

    int B      = in_sizes[0] / 1024;
    int n_mult = in_sizes[1] / 9;

    dim3 grid((B + 3) / 4, n_mult);
    lap_fwd_kernel<<<grid, TPB>>>(in, w, wf, out, B);
}

// round 14
// speedup vs baseline: 1.2102x; 1.1363x over previous
#include <cuda_runtime.h>

// Laplacian_Forward_Model — column-per-lane, smem-free, barrier-free.
// One warp per image; lane = column. Per row: one coalesced LDG.32 (128B/warp),
// vertical stencil via streaming 3-row h-window, horizontal via 2 shfls.
// Sharpen reloads x from gmem (L1D-resident). No STS/LDS/BAR at all.
//
// input (B,1,32,32) f32; weight (n_mult,9); weight_factor (n_mult,1);
// output (n_mult,B,1,32,32) f32.

#define TPB 128

// Order-preserving float<->int map (self-inverse, monotone for finite values).
__device__ __forceinline__ int f2ord(float x) {
    int b = __float_as_int(x);
    return b ^ ((b >> 31) & 0x7FFFFFFF);
}
__device__ __forceinline__ float ord2f(int k) {
    return __int_as_float(k ^ ((k >> 31) & 0x7FFFFFFF));
}
// FFMA with free [0,1] saturation.
__device__ __forceinline__ float fma_sat(float a, float b, float c) {
    float r;
    asm("fma.rn.sat.f32 %0, %1, %2, %3;" : "=f"(r) : "f"(a), "f"(b), "f"(c));
    return r;
}
// 4B streaming store (evict-first; output is never re-read).
__device__ __forceinline__ void stg_cs(float* p, float v) {
    asm volatile("st.global.cs.f32 [%0], %1;" :: "l"(p), "f"(v) : "memory");
}

__global__ __launch_bounds__(TPB, 8)
void lap_fwd_kernel(const float* __restrict__ in,
                    const float* __restrict__ weight,
                    const float* __restrict__ wfac,
                    float* __restrict__ out,
                    int B)
{
    const int tid  = threadIdx.x;
    const int wid  = tid >> 5;
    const int lane = tid & 31;
    const int b    = blockIdx.x * 4 + wid;   // image index (one per warp)
    const int ii   = blockIdx.y;
    const unsigned FULL = 0xffffffffu;

    if (b >= B) return;               // warp-uniform

    // ---- clamped 3x3 kernel (broadcast loads) ----
    float wfv = fminf(fmaxf(wfac[ii], 1.001f), 254.999f);
    float k[9];
#pragma unroll
    for (int j = 0; j < 9; ++j) {
        float w = weight[ii * 9 + j];
        k[j] = fminf(fmaxf(w, -0.999f), 0.999f) * wfv;
    }

    const float* src = in + (size_t)b * 1024 + lane;   // this lane's column

    // ---- pass 1: streaming 3x3 conv, cv[y] per lane-column ----
    // conv(y) = h0(y-1) + h1(y) + h2(y+1), ht(y) = k[3t]*L + k[3t+1]*x + k[3t+2]*R
    float cv[32];
    float h0p = 0.0f;     // h0 of previous row (row -1 = zero padding)
    float pp  = 0.0f;     // partial h0(y-1)+h1(y) awaiting h2(y+1)
#pragma unroll
    for (int y = 0; y < 32; ++y) {
        float x = src[y * 32];                     // coalesced 128B row load
        float L = __shfl_up_sync(FULL, x, 1);
        float R = __shfl_down_sync(FULL, x, 1);
        if (lane == 0)  L = 0.0f;
        if (lane == 31) R = 0.0f;
        float h0 = k[0] * L + k[1] * x + k[2] * R;
        float h1 = k[3] * L + k[4] * x + k[5] * R;
        float h2 = k[6] * L + k[7] * x + k[8] * R;
        if (y > 0) cv[y - 1] = pp + h2;
        pp  = h0p + h1;
        h0p = h0;
    }
    cv[31] = pp;                                   // h2(row 32) = 0

    // ---- reduction 1: min/max of conv over image (local tree + REDUX) ----
    float mn = cv[0], mx = cv[0];
#pragma unroll
    for (int j = 1; j < 32; ++j) { mn = fminf(mn, cv[j]); mx = fmaxf(mx, cv[j]); }
    float cmin = ord2f(__reduce_min_sync(FULL, f2ord(mn)));
    float cmax = ord2f(__reduce_max_sync(FULL, f2ord(mx)));

    // ---- pass 2: sharpen in place (x reloaded; L1D-resident) ----
    float s1 = 255.0f / fmaxf(cmax - cmin, 1e-6f);   // warp-uniform
#pragma unroll
    for (int y = 0; y < 32; ++y) {
        float x = __ldg(src + y * 32);               // L1 hit
        cv[y] = fmaf(cv[y] - cmin, s1, x);
    }

    // ---- reduction 2: min/max of sharpened ----
    mn = cv[0]; mx = cv[0];
#pragma unroll
    for (int j = 1; j < 32; ++j) { mn = fminf(mn, cv[j]); mx = fmaxf(mx, cv[j]); }
    float smin = ord2f(__reduce_min_sync(FULL, f2ord(mn)));
    float smax = ord2f(__reduce_max_sync(FULL, f2ord(mx)));

    // ---- pass 3: u = sat((sh-smin)*invd); out = floor(255*u); STG.32/row ----
    float invd = 1.0f / fminf(fmaxf(smax - smin, 1e-6f), 255.0f);
    float d2   = -smin * invd;
    float* dst = out + ((size_t)ii * B + b) * 1024 + lane;
#pragma unroll
    for (int y = 0; y < 32; ++y) {
        float u = fma_sat(cv[y], invd, d2);          // free [0,1] clamp
        stg_cs(dst + y * 32, floorf(u * 255.0f));
    }
}

extern "C" void kernel_launch(void* const* d_in, const int* in_sizes, int n_in,
                              void* d_out, int out_size)
{
    const float* in  = (const float*)d_in[0];
    const float* w   = (const float*)d_in[1];
    const float* wf  = (const float*)d_in[2];
    float* out       = (float*)d_out;

    int B      = in_sizes[0] / 1024;
    int n_mult = in_sizes[1] / 9;

    dim3 grid((B + 3) / 4, n_mult);
    lap_fwd_kernel<<<grid, TPB>>>(in, w, wf, out, B);
}